// round 15
// baseline (speedup 1.0000x reference)
#include <cuda_runtime.h>
#include <math.h>
#include <cstddef>
#include <stdint.h>

#define B_   4
#define L_   2048
#define D_   1024
#define H_   16
#define DKV  64

// Q pre-scale: (1/sqrt(64)) * log2(e)  — softmax in base-2 domain
#define QSCALE 0.18033688011112042f

// ---------------------------------------------------------------------------
// Scratch (allocation-free: __device__ globals)
// ---------------------------------------------------------------------------
static __device__ float    g_qh [(size_t)B_ * L_ * D_];   // (b,l,h*dk) natural
static __device__ float    g_kh [(size_t)B_ * L_ * D_];   // (b,l,h*dk) d 16-perm
static __device__ float    g_vh [(size_t)B_ * L_ * D_];   // (b,l,h*dv) natural
static __device__ uint16_t g_vtb[(size_t)B_ * H_ * DKV * L_]; // bf16 (bh,dv,l) tok-perm
static __device__ float    g_ctx[(size_t)B_ * L_ * D_];
static __device__ float    g_x  [(size_t)B_ * L_ * D_];
static __device__ float    g_wt [4 * 1048576];            // Wt[n][k] tf32, k 8-perm
static __device__ unsigned long long g_mp[(size_t)B_ * L_ * 32];

// ---------------------------------------------------------------------------
// Helpers
// ---------------------------------------------------------------------------
__device__ __forceinline__ uint32_t f2tf(float f) {
    uint32_t u;
    asm("cvt.rna.tf32.f32 %0, %1;" : "=r"(u) : "f"(f));
    return u;
}
__device__ __forceinline__ float rndf(float x) { return __uint_as_float(f2tf(x)); }

__device__ __forceinline__ uint16_t f2bf(float f) {
    uint16_t h;
    asm("cvt.rn.bf16.f32 %0, %1;" : "=h"(h) : "f"(f));
    return h;
}
__device__ __forceinline__ uint32_t packbf(float lo, float hi) {
    uint32_t r;
    asm("cvt.rn.bf16x2.f32 %0, %1, %2;" : "=r"(r) : "f"(hi), "f"(lo));
    return r;
}

__device__ __forceinline__ float ex2f(float x) {
    float r;
    asm("ex2.approx.ftz.f32 %0, %1;" : "=f"(r) : "f"(x));
    return r;
}

// pair-interleave perm within 8-group (GEMM Wt B-frag uint2 pairs)
__device__ __forceinline__ int perm8(int n) {
    return (n & ~7) | (((n & 3) << 1) | ((n & 7) >> 2));
}
// perm within 16-group: k -> 4*(k&3) + 2*(k>>3 & 1) + (k>>2 & 1)
// puts [S0(c), S0(c+4), S1(c), S1(c+4)] contiguous -> LDS.128 K-frags
__device__ __forceinline__ int perm16(int k) {
    int kk = k & 15;
    return (k & ~15) | ((kk & 3) << 2) | (((kk >> 3) & 1) << 1) | ((kk >> 2) & 1);
}

__device__ __forceinline__ void mma8(float4& d,
    uint32_t a0, uint32_t a1, uint32_t a2, uint32_t a3,
    uint32_t b0, uint32_t b1)
{
    asm volatile(
        "mma.sync.aligned.m16n8k8.row.col.f32.tf32.tf32.f32 "
        "{%0,%1,%2,%3}, {%4,%5,%6,%7}, {%8,%9}, {%0,%1,%2,%3};"
        : "+f"(d.x), "+f"(d.y), "+f"(d.z), "+f"(d.w)
        : "r"(a0), "r"(a1), "r"(a2), "r"(a3), "r"(b0), "r"(b1));
}

__device__ __forceinline__ void mma16(float4& d,
    uint32_t a0, uint32_t a1, uint32_t a2, uint32_t a3,
    uint32_t b0, uint32_t b1)
{
    asm volatile(
        "mma.sync.aligned.m16n8k16.row.col.f32.bf16.bf16.f32 "
        "{%0,%1,%2,%3}, {%4,%5,%6,%7}, {%8,%9}, {%0,%1,%2,%3};"
        : "+f"(d.x), "+f"(d.y), "+f"(d.z), "+f"(d.w)
        : "r"(a0), "r"(a1), "r"(a2), "r"(a3), "r"(b0), "r"(b1));
}

__device__ __forceinline__ void cp16(uint32_t dst, const void* src) {
    asm volatile("cp.async.ca.shared.global [%0], [%1], 16;" :: "r"(dst), "l"(src));
}
__device__ __forceinline__ void cpcommit() { asm volatile("cp.async.commit_group;"); }

// ---------------------------------------------------------------------------
// Weight transpose + tf32 round: Wt[n][perm8(k)] = rnd(W[k][n]); 4 mats via z
// ---------------------------------------------------------------------------
__global__ __launch_bounds__(256) void wt_kernel(
    const float* __restrict__ W0, const float* __restrict__ W1,
    const float* __restrict__ W2, const float* __restrict__ W3,
    float* __restrict__ WtBase)
{
    __shared__ float t[32][33];
    const float* W = blockIdx.z == 0 ? W0 : (blockIdx.z == 1 ? W1 :
                     (blockIdx.z == 2 ? W2 : W3));
    float* Wt = WtBase + (size_t)blockIdx.z * D_ * D_;
    const int kt = blockIdx.x * 32, nt = blockIdx.y * 32;
    const int tx = threadIdx.x & 31, ty = threadIdx.x >> 5;
#pragma unroll
    for (int r = ty; r < 32; r += 8)
        t[r][tx] = W[(size_t)(kt + r) * D_ + nt + tx];
    __syncthreads();
#pragma unroll
    for (int r = ty; r < 32; r += 8) {
        int kp = perm8(tx);
        Wt[(size_t)(nt + r) * D_ + kt + kp] = rndf(t[tx][r]);
    }
}

// ---------------------------------------------------------------------------
// V transpose: vh (b,l,h*64+dv) f32 -> vt (bh, dv, tokperm(l)) bf16
// token perm: pairs within 16-token groups pair-interleaved (perm8 on pairs)
// ---------------------------------------------------------------------------
__global__ __launch_bounds__(256) void vtrans_kernel(
    const float* __restrict__ vh, uint16_t* __restrict__ vt)
{
    __shared__ float t[32][33];
    const int l0  = blockIdx.x * 32;
    const int dv0 = blockIdx.y * 32;
    const int bh  = blockIdx.z, b = bh >> 4, h = bh & 15;
    const int tx = threadIdx.x & 31, ty = threadIdx.x >> 5;
#pragma unroll
    for (int rr = 0; rr < 4; rr++) {
        int row = ty + rr * 8;      // l index
        t[row][tx] = vh[((size_t)(b * L_ + l0 + row)) * D_ + h * DKV + dv0 + tx];
    }
    __syncthreads();
    // token perm for tx (within-16 pair interleave)
    int tg = l0 + tx;
    int pair = (tg >> 1) & 7;
    int qp = ((pair & 3) << 1) | (pair >> 2);
    int newt = (tg & ~15) | (qp << 1) | (tg & 1);
#pragma unroll
    for (int rr = 0; rr < 4; rr++) {
        int row = ty + rr * 8;      // dv index
        vt[((size_t)(bh * DKV + dv0 + row)) * L_ + newt] = f2bf(t[tx][row]);
    }
}

// ---------------------------------------------------------------------------
// Mask bit-packing
// ---------------------------------------------------------------------------
__global__ __launch_bounds__(256) void pack_mask(
    const unsigned char* __restrict__ mask, unsigned long long* __restrict__ mp)
{
    int idx = blockIdx.x * blockDim.x + threadIdx.x;
    if (idx >= B_ * L_ * 32) return;
    const unsigned* s = (const unsigned*)(mask + (size_t)idx * 64);
    unsigned long long bits = 0;
#pragma unroll
    for (int i = 0; i < 16; i++) {
        unsigned v = __ldg(s + i);
        unsigned t = ((v & 0x000000FFu) ? 1u : 0u)
                   | ((v & 0x0000FF00u) ? 2u : 0u)
                   | ((v & 0x00FF0000u) ? 4u : 0u)
                   | ((v & 0xFF000000u) ? 8u : 0u);
        bits |= (unsigned long long)t << (i * 4);
    }
    mp[idx] = bits;
}

// ---------------------------------------------------------------------------
// GEMM body: acc = A[M,K] @ Wt^T + bias. Wt [n][k] 8-perm tf32.
// 3-stage cp.async; A consumed as raw f32 (HW tf32 truncation).
// modes: 0=qh(rnd,*QSCALE) 1=kh(rnd, col perm16) 2=vh(raw) 3=out(+R raw)
// smem: As[3][128][36] + Wst[3][128][36] = 110592 B
// ---------------------------------------------------------------------------
#define GROW 36
#define GBUF (128 * GROW)    // 4608 floats per buffer per operand

__device__ __forceinline__ void gemm_body(
    const float* __restrict__ A, const float* __restrict__ Wt,
    const float* __restrict__ bias, const float* __restrict__ R,
    float* __restrict__ C, int mode, char* smraw)
{
    float* As  = (float*)smraw;              // 3*GBUF
    float* Wst = (float*)smraw + 3 * GBUF;   // 3*GBUF
    const int tid  = threadIdx.x;
    const int lane = tid & 31, wid = tid >> 5;
    const int wm = (wid & 3) * 32, wn = (wid >> 2) * 64;
    const int g = lane >> 2, c = lane & 3;
    const int bm = blockIdx.y * 128, bn = blockIdx.x * 128;
    const int K = D_, N = D_;

    uint32_t asBase = (uint32_t)__cvta_generic_to_shared(As);
    uint32_t wsBase = (uint32_t)__cvta_generic_to_shared(Wst);

    auto issue = [&](int buf, int kt) {
#pragma unroll
        for (int u = 0; u < 4; u++) {
            int i = tid + u * 256;
            int r = i >> 3, off = (i & 7) << 2;
            cp16(asBase + (uint32_t)(buf * GBUF + r * GROW + off) * 4,
                 A + (size_t)(bm + r) * K + kt + off);
        }
#pragma unroll
        for (int u = 0; u < 4; u++) {
            int i = tid + u * 256;
            int r = i >> 3, off = (i & 7) << 2;
            cp16(wsBase + (uint32_t)(buf * GBUF + r * GROW + off) * 4,
                 Wt + (size_t)(bn + r) * K + kt + off);
        }
        cpcommit();
    };

    float4 acc[2][8];
#pragma unroll
    for (int mi = 0; mi < 2; mi++)
#pragma unroll
        for (int j = 0; j < 8; j++) acc[mi][j] = make_float4(0.f, 0.f, 0.f, 0.f);

    issue(0, 0); issue(1, 32); issue(2, 64);
    for (int it = 0; it < 32; it++) {
        if (it <= 29)      asm volatile("cp.async.wait_group 2;");
        else if (it == 30) asm volatile("cp.async.wait_group 1;");
        else               asm volatile("cp.async.wait_group 0;");
        __syncthreads();
        const int buf = it - (it / 3) * 3;
        const float* Ab = As  + buf * GBUF;
        const float* Wb = Wst + buf * GBUF;
#pragma unroll
        for (int kk = 0; kk < 32; kk += 8) {
            uint32_t a[2][4];
#pragma unroll
            for (int mi = 0; mi < 2; mi++) {
                int r = wm + mi * 16;
                a[mi][0] = __float_as_uint(Ab[(r + g    ) * GROW + kk + c]);
                a[mi][1] = __float_as_uint(Ab[(r + g + 8) * GROW + kk + c]);
                a[mi][2] = __float_as_uint(Ab[(r + g    ) * GROW + kk + c + 4]);
                a[mi][3] = __float_as_uint(Ab[(r + g + 8) * GROW + kk + c + 4]);
            }
#pragma unroll
            for (int j = 0; j < 8; j++) {
                uint2 bb = *(const uint2*)&Wb[(wn + j * 8 + g) * GROW + kk + (c << 1)];
                mma8(acc[0][j], a[0][0], a[0][1], a[0][2], a[0][3], bb.x, bb.y);
                mma8(acc[1][j], a[1][0], a[1][1], a[1][2], a[1][3], bb.x, bb.y);
            }
        }
        __syncthreads();
        if (it + 3 < 32) issue(buf, (it + 3) * 32);
    }

#pragma unroll
    for (int mi = 0; mi < 2; mi++) {
#pragma unroll
        for (int j = 0; j < 8; j++) {
            int r0  = bm + wm + mi * 16 + g;
            int col = bn + wn + j * 8 + (c << 1);
            float bx = bias[col], by = bias[col + 1];
            float2 v0 = { acc[mi][j].x + bx, acc[mi][j].y + by };
            float2 v1 = { acc[mi][j].z + bx, acc[mi][j].w + by };
            if (mode == 0) {
                v0.x = rndf(v0.x * QSCALE); v0.y = rndf(v0.y * QSCALE);
                v1.x = rndf(v1.x * QSCALE); v1.y = rndf(v1.y * QSCALE);
                *(float2*)(C + (size_t)r0 * N + col)       = v0;
                *(float2*)(C + (size_t)(r0 + 8) * N + col) = v1;
            } else if (mode == 1) {
                int c0 = perm16(col), c1 = perm16(col + 1);
                C[(size_t)r0 * N + c0]       = rndf(v0.x);
                C[(size_t)r0 * N + c1]       = rndf(v0.y);
                C[(size_t)(r0 + 8) * N + c0] = rndf(v1.x);
                C[(size_t)(r0 + 8) * N + c1] = rndf(v1.y);
            } else if (mode == 2) {
                *(float2*)(C + (size_t)r0 * N + col)       = v0;
                *(float2*)(C + (size_t)(r0 + 8) * N + col) = v1;
            } else {
                float2 r0v = *(const float2*)(R + (size_t)r0 * N + col);
                float2 r1v = *(const float2*)(R + (size_t)(r0 + 8) * N + col);
                v0.x += r0v.x; v0.y += r0v.y;
                v1.x += r1v.x; v1.y += r1v.y;
                *(float2*)(C + (size_t)r0 * N + col)       = v0;
                *(float2*)(C + (size_t)(r0 + 8) * N + col) = v1;
            }
        }
    }
}

__global__ __launch_bounds__(256, 2) void qkv_gemm(
    const float* q, const float* k, const float* v,
    const float* Wtq, const float* Wtk, const float* Wtv,
    const float* bq, const float* bk, const float* bv,
    float* qh, float* kh, float* vh)
{
    extern __shared__ char sm[];
    int z = blockIdx.z;
    const float* A  = z == 0 ? q   : (z == 1 ? k   : v);
    const float* Wt = z == 0 ? Wtq : (z == 1 ? Wtk : Wtv);
    const float* b  = z == 0 ? bq  : (z == 1 ? bk  : bv);
    float*       C  = z == 0 ? qh  : (z == 1 ? kh  : vh);
    gemm_body(A, Wt, b, nullptr, C, z, sm);
}

__global__ __launch_bounds__(256, 2) void oproj_gemm(
    const float* ctx, const float* Wto, const float* bo,
    const float* R, float* C)
{
    extern __shared__ char sm[];
    gemm_body(ctx, Wto, bo, R, C, 3, sm);
}

// ---------------------------------------------------------------------------
// Fused attention: 128q block, K tiles of 64, two passes, no-max base-2
// softmax. K tf32 (perm16 in gmem, KROW=80 -> LDS.128 frags), V bf16
// (transposed + tok-perm, VROW=40 -> LDS.64 frags). PV bf16 direct-forward.
// smem (u32): Ks[2][64*80] + Vs[2][64*40] = 15360 u32 = 61440 B
// ---------------------------------------------------------------------------
#define KROW 80
#define KT32 (64 * KROW)     // 5120
#define VROW 40
#define VT32 (64 * VROW)     // 2560

__global__ __launch_bounds__(256, 2) void attn_kernel(
    const float* __restrict__ qh, const float* __restrict__ kh,
    const uint16_t* __restrict__ vt, const unsigned long long* __restrict__ mp,
    float* __restrict__ attn, float* __restrict__ ctx, int write_attn)
{
    extern __shared__ uint32_t smu[];
    uint32_t* Ks = smu;                   // 2 bufs tf32 K
    uint32_t* Vs = smu + 2 * KT32;        // 2 bufs bf16 V

    const int tid  = threadIdx.x;
    const int lane = tid & 31, wid = tid >> 5;
    const int g = lane >> 2, c = lane & 3;
    const int c2 = c << 1;
    const int q0 = blockIdx.x * 128;
    const int bh = blockIdx.y, b = bh >> 4, h = bh & 15;
    const int qw = wid * 16;

    uint32_t smemB;
    asm("{ .reg .u64 t; cvta.to.shared.u64 t, %1; cvt.u32.u64 %0, t; }"
        : "=r"(smemB) : "l"(smu));

    // Q fragments in registers (qh pre-scaled ×QSCALE, tf32, natural layout)
    uint32_t aq[8][4];
    {
        const float* qb = qh + ((size_t)(b * L_ + q0 + qw)) * D_ + h * DKV;
#pragma unroll
        for (int s = 0; s < 8; s++) {
            aq[s][0] = __float_as_uint(__ldg(qb + (size_t)g       * D_ + s * 8 + c));
            aq[s][1] = __float_as_uint(__ldg(qb + (size_t)(g + 8) * D_ + s * 8 + c));
            aq[s][2] = __float_as_uint(__ldg(qb + (size_t)g       * D_ + s * 8 + c + 4));
            aq[s][3] = __float_as_uint(__ldg(qb + (size_t)(g + 8) * D_ + s * 8 + c + 4));
        }
    }

    auto issueK = [&](int bufi, int kt) {
        const float* kb = kh + ((size_t)(b * L_ + kt)) * D_ + h * DKV;
#pragma unroll
        for (int u = 0; u < 4; u++) {
            int i = tid + u * 256;
            int r = i >> 4, coff = (i & 15) << 2;
            cp16(smemB + (uint32_t)(bufi * KT32 + r * KROW + coff) * 4,
                 kb + (size_t)r * D_ + coff);
        }
    };
    auto issueV = [&](int bufi, int kt) {
        const uint16_t* vb = vt + ((size_t)bh * DKV) * L_ + kt;
#pragma unroll
        for (int u = 0; u < 2; u++) {
            int i = tid + u * 256;
            int r = i >> 3, qq = i & 7;
            cp16(smemB + (uint32_t)((2 * KT32 + bufi * VT32 + r * VROW) * 4)
                    + (uint32_t)(qq << 4),
                 vb + (size_t)r * L_ + qq * 8);
        }
    };

    const int qg0 = q0 + qw + g;
    const int qg1 = qg0 + 8;
    const unsigned long long* mp0 = mp + (size_t)(b * L_ + qg0) * 32;
    const unsigned long long* mp1 = mp + (size_t)(b * L_ + qg1) * 32;

    float l0 = 0.f, l1 = 0.f;

    // ---------------- PASS 1: row sums of exp2 ----------------
    issueK(0, 0); cpcommit();
    int buf = 0;
    for (int kt = 0; kt < L_; kt += 64) {
        asm volatile("cp.async.wait_group 0;");
        __syncthreads();
        if (kt + 64 < L_) { issueK(buf ^ 1, kt + 64); cpcommit(); }

        const uint32_t* Kb = Ks + buf * KT32;
        float4 S[8];
#pragma unroll
        for (int j = 0; j < 8; j++) S[j] = make_float4(0.f, 0.f, 0.f, 0.f);
#pragma unroll
        for (int t = 0; t < 4; t++) {
#pragma unroll
            for (int j = 0; j < 8; j++) {
                uint4 bb = *(const uint4*)&Kb[(j * 8 + g) * KROW + t * 16 + (c << 2)];
                mma8(S[j], aq[2*t][0], aq[2*t][1], aq[2*t][2], aq[2*t][3], bb.x, bb.y);
                mma8(S[j], aq[2*t+1][0], aq[2*t+1][1], aq[2*t+1][2], aq[2*t+1][3], bb.z, bb.w);
            }
        }

        unsigned long long w0 = mp0[kt >> 6], w1 = mp1[kt >> 6];
        if (w0 | w1) {
#pragma unroll
            for (int j = 0; j < 8; j++) {
                int bi = j * 8 + c2;
                if ((w0 >> bi)       & 1) S[j].x = -INFINITY;
                if ((w0 >> (bi + 1)) & 1) S[j].y = -INFINITY;
                if ((w1 >> bi)       & 1) S[j].z = -INFINITY;
                if ((w1 >> (bi + 1)) & 1) S[j].w = -INFINITY;
            }
        }
#pragma unroll
        for (int j = 0; j < 8; j++) {
            l0 += ex2f(S[j].x) + ex2f(S[j].y);
            l1 += ex2f(S[j].z) + ex2f(S[j].w);
        }
        buf ^= 1;
    }
    l0 += __shfl_xor_sync(0xffffffffu, l0, 1);
    l0 += __shfl_xor_sync(0xffffffffu, l0, 2);
    l1 += __shfl_xor_sync(0xffffffffu, l1, 1);
    l1 += __shfl_xor_sync(0xffffffffu, l1, 2);
    const float inv0 = 1.0f / l0;
    const float inv1 = 1.0f / l1;

    // ---------------- PASS 2: attn write + O = P@V (bf16 PV) ----------------
    float4 O[8];
#pragma unroll
    for (int j = 0; j < 8; j++) O[j] = make_float4(0.f, 0.f, 0.f, 0.f);

    issueK(0, 0); issueV(0, 0); cpcommit();
    buf = 0;
    for (int kt = 0; kt < L_; kt += 64) {
        asm volatile("cp.async.wait_group 0;");
        __syncthreads();
        if (kt + 64 < L_) { issueK(buf ^ 1, kt + 64); issueV(buf ^ 1, kt + 64); cpcommit(); }

        const uint32_t* Kb = Ks + buf * KT32;
        const uint32_t* Vb = Vs + buf * VT32;
        float4 S[8];
#pragma unroll
        for (int j = 0; j < 8; j++) S[j] = make_float4(0.f, 0.f, 0.f, 0.f);
#pragma unroll
        for (int t = 0; t < 4; t++) {
#pragma unroll
            for (int j = 0; j < 8; j++) {
                uint4 bb = *(const uint4*)&Kb[(j * 8 + g) * KROW + t * 16 + (c << 2)];
                mma8(S[j], aq[2*t][0], aq[2*t][1], aq[2*t][2], aq[2*t][3], bb.x, bb.y);
                mma8(S[j], aq[2*t+1][0], aq[2*t+1][1], aq[2*t+1][2], aq[2*t+1][3], bb.z, bb.w);
            }
        }

        unsigned long long w0 = mp0[kt >> 6], w1 = mp1[kt >> 6];
        bool anymask = (w0 | w1) != 0ull;
        uint32_t pa[8], pb[8];
#pragma unroll
        for (int j = 0; j < 8; j++) {
            float px = ex2f(S[j].x) * inv0;
            float py = ex2f(S[j].y) * inv0;
            float pz = ex2f(S[j].z) * inv1;
            float pw = ex2f(S[j].w) * inv1;
            if (anymask) {
                int bi = j * 8 + c2;
                if ((w0 >> bi)       & 1) px = 0.f;
                if ((w0 >> (bi + 1)) & 1) py = 0.f;
                if ((w1 >> bi)       & 1) pz = 0.f;
                if ((w1 >> (bi + 1)) & 1) pw = 0.f;
            }
            int kcol = kt + j * 8 + c2;
            if (write_attn) {
                *(float2*)(attn + ((size_t)bh * L_ + qg0) * L_ + kcol) = make_float2(px, py);
                *(float2*)(attn + ((size_t)bh * L_ + qg1) * L_ + kcol) = make_float2(pz, pw);
            }
            pa[j] = packbf(px, py);
            pb[j] = packbf(pz, pw);
        }

        // O += P @ V : m16n8k16 bf16; B-frags LDS.64 via token-pair perm
#pragma unroll
        for (int s = 0; s < 4; s++) {
            uint32_t a0 = pa[2 * s],     a1 = pb[2 * s];
            uint32_t a2 = pa[2 * s + 1], a3 = pb[2 * s + 1];
#pragma unroll
            for (int j = 0; j < 8; j++) {
                uint2 bb = *(const uint2*)&Vb[(j * 8 + g) * VROW + s * 8 + c2];
                mma16(O[j], a0, a1, a2, a3, bb.x, bb.y);
            }
        }
        buf ^= 1;
    }

    float* cb0 = ctx + ((size_t)(b * L_ + qg0)) * D_ + h * DKV;
    float* cb1 = cb0 + (size_t)8 * D_;
#pragma unroll
    for (int j = 0; j < 8; j++) {
        int col = j * 8 + c2;
        *(float2*)(cb0 + col) = make_float2(O[j].x, O[j].y);
        *(float2*)(cb1 + col) = make_float2(O[j].z, O[j].w);
    }
}

// ---------------------------------------------------------------------------
// LayerNorm over D_=1024
// ---------------------------------------------------------------------------
__device__ __forceinline__ float warp_sum(float v) {
#pragma unroll
    for (int o = 16; o; o >>= 1) v += __shfl_xor_sync(0xffffffffu, v, o);
    return v;
}

__global__ __launch_bounds__(256) void ln_kernel(
    const float* __restrict__ X, const float* __restrict__ gamma,
    const float* __restrict__ beta, float* __restrict__ O)
{
    const float* x = X + (size_t)blockIdx.x * D_;
    const int tid = threadIdx.x;
    __shared__ float rs[8], rq[8];

    float4 v = *(const float4*)(x + tid * 4);
    float s  = v.x + v.y + v.z + v.w;
    float q2 = v.x * v.x + v.y * v.y + v.z * v.z + v.w * v.w;
    s  = warp_sum(s);
    q2 = warp_sum(q2);
    if ((tid & 31) == 0) { rs[tid >> 5] = s; rq[tid >> 5] = q2; }
    __syncthreads();
    float S = 0.f, Q = 0.f;
#pragma unroll
    for (int w = 0; w < 8; w++) { S += rs[w]; Q += rq[w]; }
    float mu  = S * (1.0f / D_);
    float var = Q * (1.0f / D_) - mu * mu;
    float inv = rsqrtf(var + 1e-5f);

    float4 gmm = *(const float4*)(gamma + tid * 4);
    float4 bb  = *(const float4*)(beta + tid * 4);
    float4 o;
    o.x = (v.x - mu) * inv * gmm.x + bb.x;
    o.y = (v.y - mu) * inv * gmm.y + bb.y;
    o.z = (v.z - mu) * inv * gmm.z + bb.z;
    o.w = (v.w - mu) * inv * gmm.w + bb.w;
    *(float4*)(O + (size_t)blockIdx.x * D_ + tid * 4) = o;
}

// ---------------------------------------------------------------------------
// Launch
// ---------------------------------------------------------------------------
extern "C" void kernel_launch(void* const* d_in, const int* in_sizes, int n_in,
                              void* d_out, int out_size)
{
    const float*         q     = (const float*)d_in[0];
    const float*         k     = (const float*)d_in[1];
    const float*         v     = (const float*)d_in[2];
    const unsigned char* mask  = (const unsigned char*)d_in[4];
    const float*         Wq    = (const float*)d_in[5];
    const float*         bq    = (const float*)d_in[6];
    const float*         Wk    = (const float*)d_in[7];
    const float*         bk    = (const float*)d_in[8];
    const float*         Wv    = (const float*)d_in[9];
    const float*         bv    = (const float*)d_in[10];
    const float*         Wo    = (const float*)d_in[11];
    const float*         bo    = (const float*)d_in[12];
    const float*         gamma = (const float*)d_in[13];
    const float*         beta  = (const float*)d_in[14];
    float*               out   = (float*)d_out;

    float *qh, *kh, *vh, *ctx, *xb, *wt;
    uint16_t* vtb;
    unsigned long long* mpck;
    cudaGetSymbolAddress((void**)&qh,   g_qh);
    cudaGetSymbolAddress((void**)&kh,   g_kh);
    cudaGetSymbolAddress((void**)&vh,   g_vh);
    cudaGetSymbolAddress((void**)&vtb,  g_vtb);
    cudaGetSymbolAddress((void**)&ctx,  g_ctx);
    cudaGetSymbolAddress((void**)&xb,   g_x);
    cudaGetSymbolAddress((void**)&wt,   g_wt);
    cudaGetSymbolAddress((void**)&mpck, g_mp);

    const size_t n_out  = (size_t)B_ * L_ * D_;
    const size_t n_attn = (size_t)B_ * H_ * L_ * L_;
    int write_attn = ((size_t)out_size >= n_out + n_attn) ? 1 : 0;
    float* attn = write_attn ? out + n_out : nullptr;

    const int GEMM_SMEM = 6 * GBUF * 4;                 // 110592
    const int ATTN_SMEM = (2 * KT32 + 2 * VT32) * 4;    // 61440
    cudaFuncSetAttribute(qkv_gemm,    cudaFuncAttributeMaxDynamicSharedMemorySize, GEMM_SMEM);
    cudaFuncSetAttribute(oproj_gemm,  cudaFuncAttributeMaxDynamicSharedMemorySize, GEMM_SMEM);
    cudaFuncSetAttribute(attn_kernel, cudaFuncAttributeMaxDynamicSharedMemorySize, ATTN_SMEM);

    wt_kernel<<<dim3(D_ / 32, D_ / 32, 4), 256>>>(Wq, Wk, Wv, Wo, wt);
    pack_mask<<<(B_ * L_ * 32 + 255) / 256, 256>>>(mask, mpck);

    const int M = B_ * L_;                 // 8192
    dim3 gqkv(D_ / 128, M / 128, 3);

    qkv_gemm<<<gqkv, 256, GEMM_SMEM>>>(q, k, v,
        wt + 0 * D_ * D_, wt + 1 * D_ * D_, wt + 2 * D_ * D_,
        bq, bk, bv, qh, kh, vh);

    vtrans_kernel<<<dim3(L_ / 32, DKV / 32, B_ * H_), 256>>>(vh, vtb);

    attn_kernel<<<dim3(L_ / 128, B_ * H_), 256, ATTN_SMEM>>>(qh, kh, vtb, mpck, attn, ctx, write_attn);

    oproj_gemm<<<dim3(D_ / 128, M / 128), 256, GEMM_SMEM>>>(ctx, wt + 3 * D_ * D_, bo, q, xb);
    ln_kernel<<<M, 256>>>(xb, gamma, beta, out);
}

// round 16
// speedup vs baseline: 1.0947x; 1.0947x over previous
#include <cuda_runtime.h>
#include <math.h>
#include <cstddef>
#include <stdint.h>

#define B_   4
#define L_   2048
#define D_   1024
#define H_   16
#define DKV  64

// Q pre-scale: (1/sqrt(64)) * log2(e)  — softmax in base-2 domain
#define QSCALE 0.18033688011112042f

// ---------------------------------------------------------------------------
// Scratch (allocation-free: __device__ globals)
// ---------------------------------------------------------------------------
static __device__ float    g_qh [(size_t)B_ * L_ * D_];   // (b,l,h*dk) natural, tf32
static __device__ float    g_kh [(size_t)B_ * L_ * D_];   // (b,l,h*dk) d 8-perm, tf32
static __device__ uint16_t g_khb[(size_t)B_ * L_ * D_];   // (b,l,h*dk) d 16b-perm, bf16
static __device__ float    g_vh [(size_t)B_ * L_ * D_];   // (b,l,h*dv) natural
static __device__ uint16_t g_vtb[(size_t)B_ * H_ * DKV * L_]; // bf16 (bh,dv,l)
static __device__ float    g_ctx[(size_t)B_ * L_ * D_];
static __device__ float    g_x  [(size_t)B_ * L_ * D_];
static __device__ float    g_wt [4 * 1048576];            // Wt[n][k] tf32, k 8-perm
static __device__ unsigned long long g_mp[(size_t)B_ * L_ * 32];

// ---------------------------------------------------------------------------
// Helpers
// ---------------------------------------------------------------------------
__device__ __forceinline__ uint32_t f2tf(float f) {
    uint32_t u;
    asm("cvt.rna.tf32.f32 %0, %1;" : "=r"(u) : "f"(f));
    return u;
}
__device__ __forceinline__ float rndf(float x) { return __uint_as_float(f2tf(x)); }

__device__ __forceinline__ uint16_t f2bf(float f) {
    uint16_t h;
    asm("cvt.rn.bf16.f32 %0, %1;" : "=h"(h) : "f"(f));
    return h;
}
// pack (lo, hi) -> bf16x2 (lo = element 0)
__device__ __forceinline__ uint32_t packbf(float lo, float hi) {
    uint32_t r;
    asm("cvt.rn.bf16x2.f32 %0, %1, %2;" : "=r"(r) : "f"(hi), "f"(lo));
    return r;
}

__device__ __forceinline__ float ex2f(float x) {
    float r;
    asm("ex2.approx.ftz.f32 %0, %1;" : "=f"(r) : "f"(x));
    return r;
}

// pair-interleave perm within 8-group (tf32 uint2 B-frag pairs)
__device__ __forceinline__ int perm8(int n) {
    return (n & ~7) | (((n & 3) << 1) | ((n & 7) >> 2));
}
// bf16 k16 B-frag perm: within 16-group, k -> 4*((k&7)>>1) + 2*(k>>3 & 1) + (k&1)
// puts (2c, 2c+1, 2c+8, 2c+9) at positions 4c..4c+3 -> (b0,b1) = one LDS.64
__device__ __forceinline__ int perm16b(int k) {
    int kk = k & 15;
    return (k & ~15) | (((kk & 7) >> 1) << 2) | (((kk >> 3) & 1) << 1) | (kk & 1);
}

__device__ __forceinline__ void mma8(float4& d,
    uint32_t a0, uint32_t a1, uint32_t a2, uint32_t a3,
    uint32_t b0, uint32_t b1)
{
    asm volatile(
        "mma.sync.aligned.m16n8k8.row.col.f32.tf32.tf32.f32 "
        "{%0,%1,%2,%3}, {%4,%5,%6,%7}, {%8,%9}, {%0,%1,%2,%3};"
        : "+f"(d.x), "+f"(d.y), "+f"(d.z), "+f"(d.w)
        : "r"(a0), "r"(a1), "r"(a2), "r"(a3), "r"(b0), "r"(b1));
}

__device__ __forceinline__ void mma16(float4& d,
    uint32_t a0, uint32_t a1, uint32_t a2, uint32_t a3,
    uint32_t b0, uint32_t b1)
{
    asm volatile(
        "mma.sync.aligned.m16n8k16.row.col.f32.bf16.bf16.f32 "
        "{%0,%1,%2,%3}, {%4,%5,%6,%7}, {%8,%9}, {%0,%1,%2,%3};"
        : "+f"(d.x), "+f"(d.y), "+f"(d.z), "+f"(d.w)
        : "r"(a0), "r"(a1), "r"(a2), "r"(a3), "r"(b0), "r"(b1));
}

__device__ __forceinline__ void cp16(uint32_t dst, const void* src) {
    asm volatile("cp.async.ca.shared.global [%0], [%1], 16;" :: "r"(dst), "l"(src));
}
__device__ __forceinline__ void cpcommit() { asm volatile("cp.async.commit_group;"); }
__device__ __forceinline__ void cpwait0()  { asm volatile("cp.async.wait_group 0;"); }
__device__ __forceinline__ void cpwait1()  { asm volatile("cp.async.wait_group 1;"); }

// ---------------------------------------------------------------------------
// Weight transpose + tf32 round: Wt[n][perm8(k)] = rnd(W[k][n]); 4 mats via z
// ---------------------------------------------------------------------------
__global__ __launch_bounds__(256) void wt_kernel(
    const float* __restrict__ W0, const float* __restrict__ W1,
    const float* __restrict__ W2, const float* __restrict__ W3,
    float* __restrict__ WtBase)
{
    __shared__ float t[32][33];
    const float* W = blockIdx.z == 0 ? W0 : (blockIdx.z == 1 ? W1 :
                     (blockIdx.z == 2 ? W2 : W3));
    float* Wt = WtBase + (size_t)blockIdx.z * D_ * D_;
    const int kt = blockIdx.x * 32, nt = blockIdx.y * 32;
    const int tx = threadIdx.x & 31, ty = threadIdx.x >> 5;
#pragma unroll
    for (int r = ty; r < 32; r += 8)
        t[r][tx] = W[(size_t)(kt + r) * D_ + nt + tx];
    __syncthreads();
#pragma unroll
    for (int r = ty; r < 32; r += 8) {
        int kp = perm8(tx);
        Wt[(size_t)(nt + r) * D_ + kt + kp] = rndf(t[tx][r]);
    }
}

// ---------------------------------------------------------------------------
// V transpose: vh (b,l,h*64+dv) f32 -> vt (bh, dv, l) bf16 (natural tokens)
// ---------------------------------------------------------------------------
__global__ __launch_bounds__(256) void vtrans_kernel(
    const float* __restrict__ vh, uint16_t* __restrict__ vt)
{
    __shared__ float t[32][33];
    const int l0  = blockIdx.x * 32;
    const int dv0 = blockIdx.y * 32;
    const int bh  = blockIdx.z, b = bh >> 4, h = bh & 15;
    const int tx = threadIdx.x & 31, ty = threadIdx.x >> 5;
#pragma unroll
    for (int rr = 0; rr < 4; rr++) {
        int row = ty + rr * 8;      // l index
        t[row][tx] = vh[((size_t)(b * L_ + l0 + row)) * D_ + h * DKV + dv0 + tx];
    }
    __syncthreads();
#pragma unroll
    for (int rr = 0; rr < 4; rr++) {
        int row = ty + rr * 8;      // dv index
        vt[((size_t)(bh * DKV + dv0 + row)) * L_ + l0 + tx] = f2bf(t[tx][row]);
    }
}

// ---------------------------------------------------------------------------
// Mask bit-packing
// ---------------------------------------------------------------------------
__global__ __launch_bounds__(256) void pack_mask(
    const unsigned char* __restrict__ mask, unsigned long long* __restrict__ mp)
{
    int idx = blockIdx.x * blockDim.x + threadIdx.x;
    if (idx >= B_ * L_ * 32) return;
    const unsigned* s = (const unsigned*)(mask + (size_t)idx * 64);
    unsigned long long bits = 0;
#pragma unroll
    for (int i = 0; i < 16; i++) {
        unsigned v = __ldg(s + i);
        unsigned t = ((v & 0x000000FFu) ? 1u : 0u)
                   | ((v & 0x0000FF00u) ? 2u : 0u)
                   | ((v & 0x00FF0000u) ? 4u : 0u)
                   | ((v & 0xFF000000u) ? 8u : 0u);
        bits |= (unsigned long long)t << (i * 4);
    }
    mp[idx] = bits;
}

// ---------------------------------------------------------------------------
// GEMM body (round-14, proven): acc = A[M,K] @ Wt^T + bias. Wt [n][k] 8-perm.
// modes: 0=qh(rnd,*QSCALE)  1=kh(rnd, perm8) + khb(bf16, perm16b)
//        2=vh(raw)  3=out(+R raw)
// smem: As[2][128][40] + Wst[2][128][36]  (77824 B)
// ---------------------------------------------------------------------------
__device__ __forceinline__ void gemm_body(
    const float* __restrict__ A, const float* __restrict__ Wt,
    const float* __restrict__ bias, const float* __restrict__ R,
    float* __restrict__ C, uint16_t* __restrict__ C2, int mode, char* smraw)
{
    float* As  = (float*)smraw;                  // 2*128*40
    float* Wst = (float*)smraw + 2 * 128 * 40;   // 2*128*36
    const int tid  = threadIdx.x;
    const int lane = tid & 31, wid = tid >> 5;
    const int wm = (wid & 3) * 32, wn = (wid >> 2) * 64;
    const int g = lane >> 2, c = lane & 3;
    const int bm = blockIdx.y * 128, bn = blockIdx.x * 128;
    const int K = D_, N = D_;

    uint32_t asBase = (uint32_t)__cvta_generic_to_shared(As);
    uint32_t wsBase = (uint32_t)__cvta_generic_to_shared(Wst);

    auto issue = [&](int buf, int kt) {
#pragma unroll
        for (int u = 0; u < 4; u++) {
            int i = tid + u * 256;
            int r = i >> 3, off = (i & 7) << 2;
            cp16(asBase + (uint32_t)(buf * 5120 + r * 40 + off) * 4,
                 A + (size_t)(bm + r) * K + kt + off);
        }
#pragma unroll
        for (int u = 0; u < 4; u++) {
            int i = tid + u * 256;
            int r = i >> 3, off = (i & 7) << 2;
            cp16(wsBase + (uint32_t)(buf * 4608 + r * 36 + off) * 4,
                 Wt + (size_t)(bn + r) * K + kt + off);
        }
        cpcommit();
    };

    float4 acc[2][8];
#pragma unroll
    for (int mi = 0; mi < 2; mi++)
#pragma unroll
        for (int j = 0; j < 8; j++) acc[mi][j] = make_float4(0.f, 0.f, 0.f, 0.f);

    issue(0, 0);
    int buf = 0;
    for (int kt = 0; kt < K; kt += 32) {
        if (kt + 32 < K) { issue(buf ^ 1, kt + 32); cpwait1(); }
        else             { cpwait0(); }
        __syncthreads();
        const float* Ab = As  + buf * 5120;
        const float* Wb = Wst + buf * 4608;
#pragma unroll
        for (int kk = 0; kk < 32; kk += 8) {
            uint32_t a[2][4];
#pragma unroll
            for (int mi = 0; mi < 2; mi++) {
                int r = wm + mi * 16;
                a[mi][0] = f2tf(Ab[(r + g    ) * 40 + kk + c]);
                a[mi][1] = f2tf(Ab[(r + g + 8) * 40 + kk + c]);
                a[mi][2] = f2tf(Ab[(r + g    ) * 40 + kk + c + 4]);
                a[mi][3] = f2tf(Ab[(r + g + 8) * 40 + kk + c + 4]);
            }
#pragma unroll
            for (int j = 0; j < 8; j++) {
                uint2 bb = *(const uint2*)&Wb[(wn + j * 8 + g) * 36 + kk + (c << 1)];
                mma8(acc[0][j], a[0][0], a[0][1], a[0][2], a[0][3], bb.x, bb.y);
                mma8(acc[1][j], a[1][0], a[1][1], a[1][2], a[1][3], bb.x, bb.y);
            }
        }
        __syncthreads();
        buf ^= 1;
    }

#pragma unroll
    for (int mi = 0; mi < 2; mi++) {
#pragma unroll
        for (int j = 0; j < 8; j++) {
            int r0  = bm + wm + mi * 16 + g;
            int col = bn + wn + j * 8 + (c << 1);
            float bx = bias[col], by = bias[col + 1];
            float2 v0 = { acc[mi][j].x + bx, acc[mi][j].y + by };
            float2 v1 = { acc[mi][j].z + bx, acc[mi][j].w + by };
            if (mode == 0) {
                v0.x = rndf(v0.x * QSCALE); v0.y = rndf(v0.y * QSCALE);
                v1.x = rndf(v1.x * QSCALE); v1.y = rndf(v1.y * QSCALE);
                *(float2*)(C + (size_t)r0 * N + col)       = v0;
                *(float2*)(C + (size_t)(r0 + 8) * N + col) = v1;
            } else if (mode == 1) {
                int c0 = perm8(col), c1 = perm8(col + 1);
                C[(size_t)r0 * N + c0]       = rndf(v0.x);
                C[(size_t)r0 * N + c1]       = rndf(v0.y);
                C[(size_t)(r0 + 8) * N + c0] = rndf(v1.x);
                C[(size_t)(r0 + 8) * N + c1] = rndf(v1.y);
                // bf16 copy for pass-1 QK^T: perm16b pairs (col even, col+1 adj)
                int p0 = perm16b(col);
                *(uint32_t*)&C2[(size_t)r0 * N + p0]       = packbf(v0.x, v0.y);
                *(uint32_t*)&C2[(size_t)(r0 + 8) * N + p0] = packbf(v1.x, v1.y);
            } else if (mode == 2) {
                *(float2*)(C + (size_t)r0 * N + col)       = v0;
                *(float2*)(C + (size_t)(r0 + 8) * N + col) = v1;
            } else {
                float2 r0v = *(const float2*)(R + (size_t)r0 * N + col);
                float2 r1v = *(const float2*)(R + (size_t)(r0 + 8) * N + col);
                v0.x += r0v.x; v0.y += r0v.y;
                v1.x += r1v.x; v1.y += r1v.y;
                *(float2*)(C + (size_t)r0 * N + col)       = v0;
                *(float2*)(C + (size_t)(r0 + 8) * N + col) = v1;
            }
        }
    }
}

__global__ __launch_bounds__(256, 2) void qkv_gemm(
    const float* q, const float* k, const float* v,
    const float* Wtq, const float* Wtk, const float* Wtv,
    const float* bq, const float* bk, const float* bv,
    float* qh, float* kh, uint16_t* khb, float* vh)
{
    extern __shared__ char sm[];
    int z = blockIdx.z;
    const float* A  = z == 0 ? q   : (z == 1 ? k   : v);
    const float* Wt = z == 0 ? Wtq : (z == 1 ? Wtk : Wtv);
    const float* b  = z == 0 ? bq  : (z == 1 ? bk  : bv);
    float*       C  = z == 0 ? qh  : (z == 1 ? kh  : vh);
    gemm_body(A, Wt, b, nullptr, C, z == 1 ? khb : nullptr, z, sm);
}

__global__ __launch_bounds__(256, 2) void oproj_gemm(
    const float* ctx, const float* Wto, const float* bo,
    const float* R, float* C)
{
    extern __shared__ char sm[];
    gemm_body(ctx, Wto, bo, R, C, nullptr, 3, sm);
}

// ---------------------------------------------------------------------------
// Fused attention: 128q block, K tiles of 64, two passes, no-max base-2
// softmax.
// PASS 1: bf16 QK^T (khb, KBROW=40 -> LDS.64 B-frags, mma16) — stats only.
// PASS 2: tf32 QK^T (kh perm8, KROW=72) + bf16 PV direct-forward (round 14).
// Pass-1 buffers alias the pass-2 region (barrier between passes).
// smem (u32): max(2*KBT, 2*KT32 + 2*VT32) = 13824 u32 = 55296 B
// ---------------------------------------------------------------------------
#define KROW 72
#define KT32 (64 * KROW)     // 4608
#define VROW 36
#define VT32 (64 * VROW)     // 2304
#define KBROW 40
#define KBT  (64 * KBROW)    // 2560

__global__ __launch_bounds__(256, 2) void attn_kernel(
    const float* __restrict__ qh, const float* __restrict__ kh,
    const uint16_t* __restrict__ khb, const uint16_t* __restrict__ vt,
    const unsigned long long* __restrict__ mp,
    float* __restrict__ attn, float* __restrict__ ctx, int write_attn)
{
    extern __shared__ uint32_t smu[];
    uint32_t* Ks = smu;                   // pass2: 2 bufs tf32 K (aliases pass1)
    uint32_t* Vs = smu + 2 * KT32;        // pass2: 2 bufs bf16 V

    const int tid  = threadIdx.x;
    const int lane = tid & 31, wid = tid >> 5;
    const int g = lane >> 2, c = lane & 3;
    const int c2 = c << 1;
    const int q0 = blockIdx.x * 128;
    const int bh = blockIdx.y, b = bh >> 4, h = bh & 15;
    const int qw = wid * 16;

    uint32_t smemB;
    asm("{ .reg .u64 t; cvta.to.shared.u64 t, %1; cvt.u32.u64 %0, t; }"
        : "=r"(smemB) : "l"(smu));

    const float* qb = qh + ((size_t)(b * L_ + q0 + qw)) * D_ + h * DKV;

    // ---- bf16 Q fragments for pass 1 (k16 layout) ----
    uint32_t aqb[4][4];
#pragma unroll
    for (int t = 0; t < 4; t++) {
        float2 x0 = *(const float2*)(qb + (size_t)g       * D_ + 16 * t + c2);
        float2 x1 = *(const float2*)(qb + (size_t)(g + 8) * D_ + 16 * t + c2);
        float2 x2 = *(const float2*)(qb + (size_t)g       * D_ + 16 * t + 8 + c2);
        float2 x3 = *(const float2*)(qb + (size_t)(g + 8) * D_ + 16 * t + 8 + c2);
        aqb[t][0] = packbf(x0.x, x0.y);
        aqb[t][1] = packbf(x1.x, x1.y);
        aqb[t][2] = packbf(x2.x, x2.y);
        aqb[t][3] = packbf(x3.x, x3.y);
    }

    auto issueKb = [&](int bufi, int kt) {   // bf16 K tile: 64 tok x 128 B
        const uint16_t* kb = khb + ((size_t)(b * L_ + kt)) * D_ + h * DKV;
#pragma unroll
        for (int u = 0; u < 2; u++) {
            int i = tid + u * 256;
            int r = i >> 3, qq = i & 7;
            cp16(smemB + (uint32_t)((bufi * KBT + r * KBROW) * 4) + (uint32_t)(qq << 4),
                 kb + (size_t)r * D_ + qq * 8);
        }
    };
    auto issueK = [&](int bufi, int kt) {    // tf32 K tile (pass 2)
        const float* kb = kh + ((size_t)(b * L_ + kt)) * D_ + h * DKV;
#pragma unroll
        for (int u = 0; u < 4; u++) {
            int i = tid + u * 256;
            int r = i >> 4, coff = (i & 15) << 2;
            cp16(smemB + (uint32_t)(bufi * KT32 + r * KROW + coff) * 4,
                 kb + (size_t)r * D_ + coff);
        }
    };
    auto issueV = [&](int bufi, int kt) {    // bf16 V tile (pass 2)
        const uint16_t* vb = vt + ((size_t)bh * DKV) * L_ + kt;
#pragma unroll
        for (int u = 0; u < 2; u++) {
            int i = tid + u * 256;
            int r = i >> 3, qq = i & 7;
            cp16(smemB + (uint32_t)((2 * KT32 + bufi * VT32 + r * VROW) * 4)
                    + (uint32_t)(qq << 4),
                 vb + (size_t)r * L_ + qq * 8);
        }
    };

    const int qg0 = q0 + qw + g;
    const int qg1 = qg0 + 8;
    const unsigned long long* mp0 = mp + (size_t)(b * L_ + qg0) * 32;
    const unsigned long long* mp1 = mp + (size_t)(b * L_ + qg1) * 32;

    float l0 = 0.f, l1 = 0.f;

    // ---------------- PASS 1: row sums of exp2 (bf16 QK^T) ----------------
    issueKb(0, 0); cpcommit();
    int buf = 0;
    for (int kt = 0; kt < L_; kt += 64) {
        cpwait0();
        __syncthreads();
        if (kt + 64 < L_) { issueKb(buf ^ 1, kt + 64); cpcommit(); }

        const uint32_t* Kb = smu + buf * KBT;
        float4 S[8];
#pragma unroll
        for (int j = 0; j < 8; j++) S[j] = make_float4(0.f, 0.f, 0.f, 0.f);
#pragma unroll
        for (int t = 0; t < 4; t++) {
#pragma unroll
            for (int j = 0; j < 8; j++) {
                uint2 bb = *(const uint2*)&Kb[(j * 8 + g) * KBROW + t * 8 + c2];
                mma16(S[j], aqb[t][0], aqb[t][1], aqb[t][2], aqb[t][3], bb.x, bb.y);
            }
        }

        unsigned long long w0 = mp0[kt >> 6], w1 = mp1[kt >> 6];
        if (w0 | w1) {
#pragma unroll
            for (int j = 0; j < 8; j++) {
                int bi = j * 8 + c2;
                if ((w0 >> bi)       & 1) S[j].x = -INFINITY;
                if ((w0 >> (bi + 1)) & 1) S[j].y = -INFINITY;
                if ((w1 >> bi)       & 1) S[j].z = -INFINITY;
                if ((w1 >> (bi + 1)) & 1) S[j].w = -INFINITY;
            }
        }
#pragma unroll
        for (int j = 0; j < 8; j++) {
            l0 += ex2f(S[j].x) + ex2f(S[j].y);
            l1 += ex2f(S[j].z) + ex2f(S[j].w);
        }
        buf ^= 1;
    }
    l0 += __shfl_xor_sync(0xffffffffu, l0, 1);
    l0 += __shfl_xor_sync(0xffffffffu, l0, 2);
    l1 += __shfl_xor_sync(0xffffffffu, l1, 1);
    l1 += __shfl_xor_sync(0xffffffffu, l1, 2);
    const float inv0 = 1.0f / l0;
    const float inv1 = 1.0f / l1;

    // ---- tf32 Q fragments for pass 2 (loaded now to limit register peak) ----
    uint32_t aq[8][4];
#pragma unroll
    for (int s = 0; s < 8; s++) {
        aq[s][0] = __float_as_uint(__ldg(qb + (size_t)g       * D_ + s * 8 + c));
        aq[s][1] = __float_as_uint(__ldg(qb + (size_t)(g + 8) * D_ + s * 8 + c));
        aq[s][2] = __float_as_uint(__ldg(qb + (size_t)g       * D_ + s * 8 + c + 4));
        aq[s][3] = __float_as_uint(__ldg(qb + (size_t)(g + 8) * D_ + s * 8 + c + 4));
    }

    __syncthreads();   // pass-1 smem reads done before aliased pass-2 fills

    // ---------------- PASS 2: attn write + O = P@V (bf16 PV) ----------------
    float4 O[8];
#pragma unroll
    for (int j = 0; j < 8; j++) O[j] = make_float4(0.f, 0.f, 0.f, 0.f);

    issueK(0, 0); issueV(0, 0); cpcommit();
    buf = 0;
    for (int kt = 0; kt < L_; kt += 64) {
        cpwait0();
        __syncthreads();
        if (kt + 64 < L_) { issueK(buf ^ 1, kt + 64); issueV(buf ^ 1, kt + 64); cpcommit(); }

        const uint32_t* Kb = Ks + buf * KT32;
        const uint32_t* Vb = Vs + buf * VT32;
        float4 S[8];
#pragma unroll
        for (int j = 0; j < 8; j++) S[j] = make_float4(0.f, 0.f, 0.f, 0.f);
#pragma unroll
        for (int s = 0; s < 8; s++) {
#pragma unroll
            for (int j = 0; j < 8; j++) {
                uint2 bb = *(const uint2*)&Kb[(j * 8 + g) * KROW + s * 8 + c2];
                mma8(S[j], aq[s][0], aq[s][1], aq[s][2], aq[s][3], bb.x, bb.y);
            }
        }

        unsigned long long w0 = mp0[kt >> 6], w1 = mp1[kt >> 6];
        bool anymask = (w0 | w1) != 0ull;
        uint32_t pa[8], pb[8];
#pragma unroll
        for (int j = 0; j < 8; j++) {
            float px = ex2f(S[j].x) * inv0;
            float py = ex2f(S[j].y) * inv0;
            float pz = ex2f(S[j].z) * inv1;
            float pw = ex2f(S[j].w) * inv1;
            if (anymask) {
                int bi = j * 8 + c2;
                if ((w0 >> bi)       & 1) px = 0.f;
                if ((w0 >> (bi + 1)) & 1) py = 0.f;
                if ((w1 >> bi)       & 1) pz = 0.f;
                if ((w1 >> (bi + 1)) & 1) pw = 0.f;
            }
            int kcol = kt + j * 8 + c2;
            if (write_attn) {
                *(float2*)(attn + ((size_t)bh * L_ + qg0) * L_ + kcol) = make_float2(px, py);
                *(float2*)(attn + ((size_t)bh * L_ + qg1) * L_ + kcol) = make_float2(pz, pw);
            }
            pa[j] = packbf(px, py);
            pb[j] = packbf(pz, pw);
        }

        // O += P @ V : m16n8k16 bf16; A-frags direct from pa/pb
#pragma unroll
        for (int s = 0; s < 4; s++) {
            uint32_t a0 = pa[2 * s],     a1 = pb[2 * s];
            uint32_t a2 = pa[2 * s + 1], a3 = pb[2 * s + 1];
#pragma unroll
            for (int j = 0; j < 8; j++) {
                uint32_t b0 = Vb[(j * 8 + g) * VROW + s * 8 + c];
                uint32_t b1 = Vb[(j * 8 + g) * VROW + s * 8 + c + 4];
                mma16(O[j], a0, a1, a2, a3, b0, b1);
            }
        }
        buf ^= 1;
    }

    float* cb0 = ctx + ((size_t)(b * L_ + qg0)) * D_ + h * DKV;
    float* cb1 = cb0 + (size_t)8 * D_;
#pragma unroll
    for (int j = 0; j < 8; j++) {
        int col = j * 8 + c2;
        *(float2*)(cb0 + col) = make_float2(O[j].x, O[j].y);
        *(float2*)(cb1 + col) = make_float2(O[j].z, O[j].w);
    }
}

// ---------------------------------------------------------------------------
// LayerNorm over D_=1024
// ---------------------------------------------------------------------------
__device__ __forceinline__ float warp_sum(float v) {
#pragma unroll
    for (int o = 16; o; o >>= 1) v += __shfl_xor_sync(0xffffffffu, v, o);
    return v;
}

__global__ __launch_bounds__(256) void ln_kernel(
    const float* __restrict__ X, const float* __restrict__ gamma,
    const float* __restrict__ beta, float* __restrict__ O)
{
    const float* x = X + (size_t)blockIdx.x * D_;
    const int tid = threadIdx.x;
    __shared__ float rs[8], rq[8];

    float4 v = *(const float4*)(x + tid * 4);
    float s  = v.x + v.y + v.z + v.w;
    float q2 = v.x * v.x + v.y * v.y + v.z * v.z + v.w * v.w;
    s  = warp_sum(s);
    q2 = warp_sum(q2);
    if ((tid & 31) == 0) { rs[tid >> 5] = s; rq[tid >> 5] = q2; }
    __syncthreads();
    float S = 0.f, Q = 0.f;
#pragma unroll
    for (int w = 0; w < 8; w++) { S += rs[w]; Q += rq[w]; }
    float mu  = S * (1.0f / D_);
    float var = Q * (1.0f / D_) - mu * mu;
    float inv = rsqrtf(var + 1e-5f);

    float4 gmm = *(const float4*)(gamma + tid * 4);
    float4 bb  = *(const float4*)(beta + tid * 4);
    float4 o;
    o.x = (v.x - mu) * inv * gmm.x + bb.x;
    o.y = (v.y - mu) * inv * gmm.y + bb.y;
    o.z = (v.z - mu) * inv * gmm.z + bb.z;
    o.w = (v.w - mu) * inv * gmm.w + bb.w;
    *(float4*)(O + (size_t)blockIdx.x * D_ + tid * 4) = o;
}

// ---------------------------------------------------------------------------
// Launch
// ---------------------------------------------------------------------------
extern "C" void kernel_launch(void* const* d_in, const int* in_sizes, int n_in,
                              void* d_out, int out_size)
{
    const float*         q     = (const float*)d_in[0];
    const float*         k     = (const float*)d_in[1];
    const float*         v     = (const float*)d_in[2];
    const unsigned char* mask  = (const unsigned char*)d_in[4];
    const float*         Wq    = (const float*)d_in[5];
    const float*         bq    = (const float*)d_in[6];
    const float*         Wk    = (const float*)d_in[7];
    const float*         bk    = (const float*)d_in[8];
    const float*         Wv    = (const float*)d_in[9];
    const float*         bv    = (const float*)d_in[10];
    const float*         Wo    = (const float*)d_in[11];
    const float*         bo    = (const float*)d_in[12];
    const float*         gamma = (const float*)d_in[13];
    const float*         beta  = (const float*)d_in[14];
    float*               out   = (float*)d_out;

    float *qh, *kh, *vh, *ctx, *xb, *wt;
    uint16_t *vtb, *khb;
    unsigned long long* mpck;
    cudaGetSymbolAddress((void**)&qh,   g_qh);
    cudaGetSymbolAddress((void**)&kh,   g_kh);
    cudaGetSymbolAddress((void**)&khb,  g_khb);
    cudaGetSymbolAddress((void**)&vh,   g_vh);
    cudaGetSymbolAddress((void**)&vtb,  g_vtb);
    cudaGetSymbolAddress((void**)&ctx,  g_ctx);
    cudaGetSymbolAddress((void**)&xb,   g_x);
    cudaGetSymbolAddress((void**)&wt,   g_wt);
    cudaGetSymbolAddress((void**)&mpck, g_mp);

    const size_t n_out  = (size_t)B_ * L_ * D_;
    const size_t n_attn = (size_t)B_ * H_ * L_ * L_;
    int write_attn = ((size_t)out_size >= n_out + n_attn) ? 1 : 0;
    float* attn = write_attn ? out + n_out : nullptr;

    const int GEMM_SMEM = (2 * 128 * 40 + 2 * 128 * 36) * 4;   // 77824
    const int ATTN_SMEM = (2 * KT32 + 2 * VT32) * 4;           // 55296
    cudaFuncSetAttribute(qkv_gemm,    cudaFuncAttributeMaxDynamicSharedMemorySize, GEMM_SMEM);
    cudaFuncSetAttribute(oproj_gemm,  cudaFuncAttributeMaxDynamicSharedMemorySize, GEMM_SMEM);
    cudaFuncSetAttribute(attn_kernel, cudaFuncAttributeMaxDynamicSharedMemorySize, ATTN_SMEM);

    wt_kernel<<<dim3(D_ / 32, D_ / 32, 4), 256>>>(Wq, Wk, Wv, Wo, wt);
    pack_mask<<<(B_ * L_ * 32 + 255) / 256, 256>>>(mask, mpck);

    const int M = B_ * L_;                 // 8192
    dim3 gqkv(D_ / 128, M / 128, 3);

    qkv_gemm<<<gqkv, 256, GEMM_SMEM>>>(q, k, v,
        wt + 0 * D_ * D_, wt + 1 * D_ * D_, wt + 2 * D_ * D_,
        bq, bk, bv, qh, kh, khb, vh);

    vtrans_kernel<<<dim3(L_ / 32, DKV / 32, B_ * H_), 256>>>(vh, vtb);

    attn_kernel<<<dim3(L_ / 128, B_ * H_), 256, ATTN_SMEM>>>(qh, kh, khb, vtb, mpck, attn, ctx, write_attn);

    oproj_gemm<<<dim3(D_ / 128, M / 128), 256, GEMM_SMEM>>>(ctx, wt + 3 * D_ * D_, bo, q, xb);
    ln_kernel<<<M, 256>>>(xb, gamma, beta, out);
}

// round 17
// speedup vs baseline: 1.1043x; 1.0088x over previous
#include <cuda_runtime.h>
#include <math.h>
#include <cstddef>
#include <stdint.h>

#define B_   4
#define L_   2048
#define D_   1024
#define H_   16
#define DKV  64

// Q pre-scale: (1/sqrt(64)) * log2(e)  — softmax in base-2 domain
#define QSCALE 0.18033688011112042f

// ---------------------------------------------------------------------------
// Scratch (allocation-free: __device__ globals)
// ---------------------------------------------------------------------------
static __device__ float    g_ap [(size_t)3 * B_ * L_ * D_]; // q,k,v perm8+tf32
static __device__ float    g_qh [(size_t)B_ * L_ * D_];   // (b,l,h*dk) natural, tf32
static __device__ float    g_kh [(size_t)B_ * L_ * D_];   // (b,l,h*dk) d 8-perm, tf32
static __device__ uint16_t g_khb[(size_t)B_ * L_ * D_];   // (b,l,h*dk) d 16b-perm, bf16
static __device__ float    g_vh [(size_t)B_ * L_ * D_];   // (b,l,h*dv) natural
static __device__ uint16_t g_vtb[(size_t)B_ * H_ * DKV * L_]; // bf16 (bh,dv,l)
static __device__ float    g_ctx[(size_t)B_ * L_ * D_];   // d 8-perm, tf32
static __device__ float    g_x  [(size_t)B_ * L_ * D_];
static __device__ float    g_wt [4 * 1048576];            // Wt[n][k] tf32, k 8-perm
static __device__ unsigned long long g_mp[(size_t)B_ * L_ * 32];

// ---------------------------------------------------------------------------
// Helpers
// ---------------------------------------------------------------------------
__device__ __forceinline__ uint32_t f2tf(float f) {
    uint32_t u;
    asm("cvt.rna.tf32.f32 %0, %1;" : "=r"(u) : "f"(f));
    return u;
}
__device__ __forceinline__ float rndf(float x) { return __uint_as_float(f2tf(x)); }

__device__ __forceinline__ uint16_t f2bf(float f) {
    uint16_t h;
    asm("cvt.rn.bf16.f32 %0, %1;" : "=h"(h) : "f"(f));
    return h;
}
// pack (lo, hi) -> bf16x2 (lo = element 0)
__device__ __forceinline__ uint32_t packbf(float lo, float hi) {
    uint32_t r;
    asm("cvt.rn.bf16x2.f32 %0, %1, %2;" : "=r"(r) : "f"(hi), "f"(lo));
    return r;
}

__device__ __forceinline__ float ex2f(float x) {
    float r;
    asm("ex2.approx.ftz.f32 %0, %1;" : "=f"(r) : "f"(x));
    return r;
}

// pair-interleave perm within 8-group: element e -> position (e<4 ? 2e : 2(e-4)+1)
__device__ __forceinline__ int perm8(int n) {
    return (n & ~7) | (((n & 3) << 1) | ((n & 7) >> 2));
}
// bf16 k16 B-frag perm (pass-1 K): within 16-group
__device__ __forceinline__ int perm16b(int k) {
    int kk = k & 15;
    return (k & ~15) | (((kk & 7) >> 1) << 2) | (((kk >> 3) & 1) << 1) | (kk & 1);
}

__device__ __forceinline__ void mma8(float4& d,
    uint32_t a0, uint32_t a1, uint32_t a2, uint32_t a3,
    uint32_t b0, uint32_t b1)
{
    asm volatile(
        "mma.sync.aligned.m16n8k8.row.col.f32.tf32.tf32.f32 "
        "{%0,%1,%2,%3}, {%4,%5,%6,%7}, {%8,%9}, {%0,%1,%2,%3};"
        : "+f"(d.x), "+f"(d.y), "+f"(d.z), "+f"(d.w)
        : "r"(a0), "r"(a1), "r"(a2), "r"(a3), "r"(b0), "r"(b1));
}

__device__ __forceinline__ void mma16(float4& d,
    uint32_t a0, uint32_t a1, uint32_t a2, uint32_t a3,
    uint32_t b0, uint32_t b1)
{
    asm volatile(
        "mma.sync.aligned.m16n8k16.row.col.f32.bf16.bf16.f32 "
        "{%0,%1,%2,%3}, {%4,%5,%6,%7}, {%8,%9}, {%0,%1,%2,%3};"
        : "+f"(d.x), "+f"(d.y), "+f"(d.z), "+f"(d.w)
        : "r"(a0), "r"(a1), "r"(a2), "r"(a3), "r"(b0), "r"(b1));
}

__device__ __forceinline__ void cp16(uint32_t dst, const void* src) {
    asm volatile("cp.async.ca.shared.global [%0], [%1], 16;" :: "r"(dst), "l"(src));
}
__device__ __forceinline__ void cpcommit() { asm volatile("cp.async.commit_group;"); }
__device__ __forceinline__ void cpwait0()  { asm volatile("cp.async.wait_group 0;"); }
__device__ __forceinline__ void cpwait1()  { asm volatile("cp.async.wait_group 1;"); }

// ---------------------------------------------------------------------------
// A-operand prep: out = rnd(perm8_within_8(in)) for q,k,v (grid.z selects)
// stored[2e]=in[e] (e<4), stored[2(e-4)+1]=in[e] (e>=4)
// ---------------------------------------------------------------------------
__global__ __launch_bounds__(256) void aperm_kernel(
    const float* __restrict__ q, const float* __restrict__ k,
    const float* __restrict__ v, float* __restrict__ outBase)
{
    const float* in = blockIdx.z == 0 ? q : (blockIdx.z == 1 ? k : v);
    float* out = outBase + (size_t)blockIdx.z * B_ * L_ * D_;
    size_t i8 = ((size_t)blockIdx.x * 256 + threadIdx.x) * 8;
    float4 e0 = *(const float4*)(in + i8);       // e0..e3
    float4 e1 = *(const float4*)(in + i8 + 4);   // e4..e7
    float4 o0, o1;
    o0.x = rndf(e0.x); o0.y = rndf(e1.x); o0.z = rndf(e0.y); o0.w = rndf(e1.y);
    o1.x = rndf(e0.z); o1.y = rndf(e1.z); o1.z = rndf(e0.w); o1.w = rndf(e1.w);
    *(float4*)(out + i8)     = o0;
    *(float4*)(out + i8 + 4) = o1;
}

// ---------------------------------------------------------------------------
// Weight transpose + tf32 round: Wt[n][perm8(k)] = rnd(W[k][n]); 4 mats via z
// ---------------------------------------------------------------------------
__global__ __launch_bounds__(256) void wt_kernel(
    const float* __restrict__ W0, const float* __restrict__ W1,
    const float* __restrict__ W2, const float* __restrict__ W3,
    float* __restrict__ WtBase)
{
    __shared__ float t[32][33];
    const float* W = blockIdx.z == 0 ? W0 : (blockIdx.z == 1 ? W1 :
                     (blockIdx.z == 2 ? W2 : W3));
    float* Wt = WtBase + (size_t)blockIdx.z * D_ * D_;
    const int kt = blockIdx.x * 32, nt = blockIdx.y * 32;
    const int tx = threadIdx.x & 31, ty = threadIdx.x >> 5;
#pragma unroll
    for (int r = ty; r < 32; r += 8)
        t[r][tx] = W[(size_t)(kt + r) * D_ + nt + tx];
    __syncthreads();
#pragma unroll
    for (int r = ty; r < 32; r += 8) {
        int kp = perm8(tx);
        Wt[(size_t)(nt + r) * D_ + kt + kp] = rndf(t[tx][r]);
    }
}

// ---------------------------------------------------------------------------
// V transpose: vh (b,l,h*64+dv) f32 -> vt (bh, dv, l) bf16 (natural tokens)
// ---------------------------------------------------------------------------
__global__ __launch_bounds__(256) void vtrans_kernel(
    const float* __restrict__ vh, uint16_t* __restrict__ vt)
{
    __shared__ float t[32][33];
    const int l0  = blockIdx.x * 32;
    const int dv0 = blockIdx.y * 32;
    const int bh  = blockIdx.z, b = bh >> 4, h = bh & 15;
    const int tx = threadIdx.x & 31, ty = threadIdx.x >> 5;
#pragma unroll
    for (int rr = 0; rr < 4; rr++) {
        int row = ty + rr * 8;      // l index
        t[row][tx] = vh[((size_t)(b * L_ + l0 + row)) * D_ + h * DKV + dv0 + tx];
    }
    __syncthreads();
#pragma unroll
    for (int rr = 0; rr < 4; rr++) {
        int row = ty + rr * 8;      // dv index
        vt[((size_t)(bh * DKV + dv0 + row)) * L_ + l0 + tx] = f2bf(t[tx][row]);
    }
}

// ---------------------------------------------------------------------------
// Mask bit-packing
// ---------------------------------------------------------------------------
__global__ __launch_bounds__(256) void pack_mask(
    const unsigned char* __restrict__ mask, unsigned long long* __restrict__ mp)
{
    int idx = blockIdx.x * blockDim.x + threadIdx.x;
    if (idx >= B_ * L_ * 32) return;
    const unsigned* s = (const unsigned*)(mask + (size_t)idx * 64);
    unsigned long long bits = 0;
#pragma unroll
    for (int i = 0; i < 16; i++) {
        unsigned v = __ldg(s + i);
        unsigned t = ((v & 0x000000FFu) ? 1u : 0u)
                   | ((v & 0x0000FF00u) ? 2u : 0u)
                   | ((v & 0x00FF0000u) ? 4u : 0u)
                   | ((v & 0xFF000000u) ? 8u : 0u);
        bits |= (unsigned long long)t << (i * 4);
    }
    mp[idx] = bits;
}

// ---------------------------------------------------------------------------
// GEMM body: acc = A[M,K] @ Wt^T + bias. BOTH A and Wt are k 8-perm, tf32
// pre-rounded -> A-frags are LDS.64 pairs, no in-loop cvt.
// modes: 0=qh(rnd,*QSCALE)  1=kh(rnd, perm8) + khb(bf16, perm16b)
//        2=vh(raw)  3=out(+R raw)
// smem: As[2][128][40] + Wst[2][128][36]  (77824 B)
// ---------------------------------------------------------------------------
__device__ __forceinline__ void gemm_body(
    const float* __restrict__ A, const float* __restrict__ Wt,
    const float* __restrict__ bias, const float* __restrict__ R,
    float* __restrict__ C, uint16_t* __restrict__ C2, int mode, char* smraw)
{
    float* As  = (float*)smraw;                  // 2*128*40
    float* Wst = (float*)smraw + 2 * 128 * 40;   // 2*128*36
    const int tid  = threadIdx.x;
    const int lane = tid & 31, wid = tid >> 5;
    const int wm = (wid & 3) * 32, wn = (wid >> 2) * 64;
    const int g = lane >> 2, c = lane & 3;
    const int c2 = c << 1;
    const int bm = blockIdx.y * 128, bn = blockIdx.x * 128;
    const int K = D_, N = D_;

    uint32_t asBase = (uint32_t)__cvta_generic_to_shared(As);
    uint32_t wsBase = (uint32_t)__cvta_generic_to_shared(Wst);

    auto issue = [&](int buf, int kt) {
#pragma unroll
        for (int u = 0; u < 4; u++) {
            int i = tid + u * 256;
            int r = i >> 3, off = (i & 7) << 2;
            cp16(asBase + (uint32_t)(buf * 5120 + r * 40 + off) * 4,
                 A + (size_t)(bm + r) * K + kt + off);
        }
#pragma unroll
        for (int u = 0; u < 4; u++) {
            int i = tid + u * 256;
            int r = i >> 3, off = (i & 7) << 2;
            cp16(wsBase + (uint32_t)(buf * 4608 + r * 36 + off) * 4,
                 Wt + (size_t)(bn + r) * K + kt + off);
        }
        cpcommit();
    };

    float4 acc[2][8];
#pragma unroll
    for (int mi = 0; mi < 2; mi++)
#pragma unroll
        for (int j = 0; j < 8; j++) acc[mi][j] = make_float4(0.f, 0.f, 0.f, 0.f);

    issue(0, 0);
    int buf = 0;
    for (int kt = 0; kt < K; kt += 32) {
        if (kt + 32 < K) { issue(buf ^ 1, kt + 32); cpwait1(); }
        else             { cpwait0(); }
        __syncthreads();
        const float* Ab = As  + buf * 5120;
        const float* Wb = Wst + buf * 4608;
#pragma unroll
        for (int kk = 0; kk < 32; kk += 8) {
            uint2 a0[2], a1[2];   // a0[mi] = (k=c, k=c+4) row wm+mi*16+g; a1 = +8
#pragma unroll
            for (int mi = 0; mi < 2; mi++) {
                int r = wm + mi * 16;
                a0[mi] = *(const uint2*)&Ab[(r + g    ) * 40 + kk + c2];
                a1[mi] = *(const uint2*)&Ab[(r + g + 8) * 40 + kk + c2];
            }
#pragma unroll
            for (int j = 0; j < 8; j++) {
                uint2 bb = *(const uint2*)&Wb[(wn + j * 8 + g) * 36 + kk + c2];
                mma8(acc[0][j], a0[0].x, a1[0].x, a0[0].y, a1[0].y, bb.x, bb.y);
                mma8(acc[1][j], a0[1].x, a1[1].x, a0[1].y, a1[1].y, bb.x, bb.y);
            }
        }
        __syncthreads();
        buf ^= 1;
    }

#pragma unroll
    for (int mi = 0; mi < 2; mi++) {
#pragma unroll
        for (int j = 0; j < 8; j++) {
            int r0  = bm + wm + mi * 16 + g;
            int col = bn + wn + j * 8 + c2;
            float bx = bias[col], by = bias[col + 1];
            float2 v0 = { acc[mi][j].x + bx, acc[mi][j].y + by };
            float2 v1 = { acc[mi][j].z + bx, acc[mi][j].w + by };
            if (mode == 0) {
                v0.x = rndf(v0.x * QSCALE); v0.y = rndf(v0.y * QSCALE);
                v1.x = rndf(v1.x * QSCALE); v1.y = rndf(v1.y * QSCALE);
                *(float2*)(C + (size_t)r0 * N + col)       = v0;
                *(float2*)(C + (size_t)(r0 + 8) * N + col) = v1;
            } else if (mode == 1) {
                int c0 = perm8(col), c1 = perm8(col + 1);
                C[(size_t)r0 * N + c0]       = rndf(v0.x);
                C[(size_t)r0 * N + c1]       = rndf(v0.y);
                C[(size_t)(r0 + 8) * N + c0] = rndf(v1.x);
                C[(size_t)(r0 + 8) * N + c1] = rndf(v1.y);
                int p0 = perm16b(col);
                *(uint32_t*)&C2[(size_t)r0 * N + p0]       = packbf(v0.x, v0.y);
                *(uint32_t*)&C2[(size_t)(r0 + 8) * N + p0] = packbf(v1.x, v1.y);
            } else if (mode == 2) {
                *(float2*)(C + (size_t)r0 * N + col)       = v0;
                *(float2*)(C + (size_t)(r0 + 8) * N + col) = v1;
            } else {
                float2 r0v = *(const float2*)(R + (size_t)r0 * N + col);
                float2 r1v = *(const float2*)(R + (size_t)(r0 + 8) * N + col);
                v0.x += r0v.x; v0.y += r0v.y;
                v1.x += r1v.x; v1.y += r1v.y;
                *(float2*)(C + (size_t)r0 * N + col)       = v0;
                *(float2*)(C + (size_t)(r0 + 8) * N + col) = v1;
            }
        }
    }
}

__global__ __launch_bounds__(256, 2) void qkv_gemm(
    const float* qp, const float* kp, const float* vp,
    const float* Wtq, const float* Wtk, const float* Wtv,
    const float* bq, const float* bk, const float* bv,
    float* qh, float* kh, uint16_t* khb, float* vh)
{
    extern __shared__ char sm[];
    int z = blockIdx.z;
    const float* A  = z == 0 ? qp  : (z == 1 ? kp  : vp);
    const float* Wt = z == 0 ? Wtq : (z == 1 ? Wtk : Wtv);
    const float* b  = z == 0 ? bq  : (z == 1 ? bk  : bv);
    float*       C  = z == 0 ? qh  : (z == 1 ? kh  : vh);
    gemm_body(A, Wt, b, nullptr, C, z == 1 ? khb : nullptr, z, sm);
}

__global__ __launch_bounds__(256, 2) void oproj_gemm(
    const float* ctx, const float* Wto, const float* bo,
    const float* R, float* C)
{
    extern __shared__ char sm[];
    gemm_body(ctx, Wto, bo, R, C, nullptr, 3, sm);
}

// ---------------------------------------------------------------------------
// Fused attention (round-16 structure):
// PASS 1: bf16 QK^T (khb, KBROW=40, mma16) — stats only.
// PASS 2: tf32 QK^T (kh perm8, KROW=72) + bf16 PV direct-forward.
// ctx written perm8(d) + tf32-rounded for the oproj A-operand path.
// smem (u32): 2*KT32 + 2*VT32 = 13824 u32 = 55296 B (pass 1 aliases)
// ---------------------------------------------------------------------------
#define KROW 72
#define KT32 (64 * KROW)     // 4608
#define VROW 36
#define VT32 (64 * VROW)     // 2304
#define KBROW 40
#define KBT  (64 * KBROW)    // 2560

__global__ __launch_bounds__(256, 2) void attn_kernel(
    const float* __restrict__ qh, const float* __restrict__ kh,
    const uint16_t* __restrict__ khb, const uint16_t* __restrict__ vt,
    const unsigned long long* __restrict__ mp,
    float* __restrict__ attn, float* __restrict__ ctx, int write_attn)
{
    extern __shared__ uint32_t smu[];
    uint32_t* Ks = smu;                   // pass2: 2 bufs tf32 K (aliases pass1)
    uint32_t* Vs = smu + 2 * KT32;        // pass2: 2 bufs bf16 V

    const int tid  = threadIdx.x;
    const int lane = tid & 31, wid = tid >> 5;
    const int g = lane >> 2, c = lane & 3;
    const int c2 = c << 1;
    const int q0 = blockIdx.x * 128;
    const int bh = blockIdx.y, b = bh >> 4, h = bh & 15;
    const int qw = wid * 16;

    uint32_t smemB;
    asm("{ .reg .u64 t; cvta.to.shared.u64 t, %1; cvt.u32.u64 %0, t; }"
        : "=r"(smemB) : "l"(smu));

    const float* qb = qh + ((size_t)(b * L_ + q0 + qw)) * D_ + h * DKV;

    // ---- bf16 Q fragments for pass 1 (k16 layout) ----
    uint32_t aqb[4][4];
#pragma unroll
    for (int t = 0; t < 4; t++) {
        float2 x0 = *(const float2*)(qb + (size_t)g       * D_ + 16 * t + c2);
        float2 x1 = *(const float2*)(qb + (size_t)(g + 8) * D_ + 16 * t + c2);
        float2 x2 = *(const float2*)(qb + (size_t)g       * D_ + 16 * t + 8 + c2);
        float2 x3 = *(const float2*)(qb + (size_t)(g + 8) * D_ + 16 * t + 8 + c2);
        aqb[t][0] = packbf(x0.x, x0.y);
        aqb[t][1] = packbf(x1.x, x1.y);
        aqb[t][2] = packbf(x2.x, x2.y);
        aqb[t][3] = packbf(x3.x, x3.y);
    }

    auto issueKb = [&](int bufi, int kt) {   // bf16 K tile: 64 tok x 128 B
        const uint16_t* kb = khb + ((size_t)(b * L_ + kt)) * D_ + h * DKV;
#pragma unroll
        for (int u = 0; u < 2; u++) {
            int i = tid + u * 256;
            int r = i >> 3, qq = i & 7;
            cp16(smemB + (uint32_t)((bufi * KBT + r * KBROW) * 4) + (uint32_t)(qq << 4),
                 kb + (size_t)r * D_ + qq * 8);
        }
    };
    auto issueK = [&](int bufi, int kt) {    // tf32 K tile (pass 2)
        const float* kb = kh + ((size_t)(b * L_ + kt)) * D_ + h * DKV;
#pragma unroll
        for (int u = 0; u < 4; u++) {
            int i = tid + u * 256;
            int r = i >> 4, coff = (i & 15) << 2;
            cp16(smemB + (uint32_t)(bufi * KT32 + r * KROW + coff) * 4,
                 kb + (size_t)r * D_ + coff);
        }
    };
    auto issueV = [&](int bufi, int kt) {    // bf16 V tile (pass 2)
        const uint16_t* vb = vt + ((size_t)bh * DKV) * L_ + kt;
#pragma unroll
        for (int u = 0; u < 2; u++) {
            int i = tid + u * 256;
            int r = i >> 3, qq = i & 7;
            cp16(smemB + (uint32_t)((2 * KT32 + bufi * VT32 + r * VROW) * 4)
                    + (uint32_t)(qq << 4),
                 vb + (size_t)r * L_ + qq * 8);
        }
    };

    const int qg0 = q0 + qw + g;
    const int qg1 = qg0 + 8;
    const unsigned long long* mp0 = mp + (size_t)(b * L_ + qg0) * 32;
    const unsigned long long* mp1 = mp + (size_t)(b * L_ + qg1) * 32;

    float l0 = 0.f, l1 = 0.f;

    // ---------------- PASS 1: row sums of exp2 (bf16 QK^T) ----------------
    issueKb(0, 0); cpcommit();
    int buf = 0;
    for (int kt = 0; kt < L_; kt += 64) {
        cpwait0();
        __syncthreads();
        if (kt + 64 < L_) { issueKb(buf ^ 1, kt + 64); cpcommit(); }

        const uint32_t* Kb = smu + buf * KBT;
        float4 S[8];
#pragma unroll
        for (int j = 0; j < 8; j++) S[j] = make_float4(0.f, 0.f, 0.f, 0.f);
#pragma unroll
        for (int t = 0; t < 4; t++) {
#pragma unroll
            for (int j = 0; j < 8; j++) {
                uint2 bb = *(const uint2*)&Kb[(j * 8 + g) * KBROW + t * 8 + c2];
                mma16(S[j], aqb[t][0], aqb[t][1], aqb[t][2], aqb[t][3], bb.x, bb.y);
            }
        }

        unsigned long long w0 = mp0[kt >> 6], w1 = mp1[kt >> 6];
        if (w0 | w1) {
#pragma unroll
            for (int j = 0; j < 8; j++) {
                int bi = j * 8 + c2;
                if ((w0 >> bi)       & 1) S[j].x = -INFINITY;
                if ((w0 >> (bi + 1)) & 1) S[j].y = -INFINITY;
                if ((w1 >> bi)       & 1) S[j].z = -INFINITY;
                if ((w1 >> (bi + 1)) & 1) S[j].w = -INFINITY;
            }
        }
#pragma unroll
        for (int j = 0; j < 8; j++) {
            l0 += ex2f(S[j].x) + ex2f(S[j].y);
            l1 += ex2f(S[j].z) + ex2f(S[j].w);
        }
        buf ^= 1;
    }
    l0 += __shfl_xor_sync(0xffffffffu, l0, 1);
    l0 += __shfl_xor_sync(0xffffffffu, l0, 2);
    l1 += __shfl_xor_sync(0xffffffffu, l1, 1);
    l1 += __shfl_xor_sync(0xffffffffu, l1, 2);
    const float inv0 = 1.0f / l0;
    const float inv1 = 1.0f / l1;

    // ---- tf32 Q fragments for pass 2 ----
    uint32_t aq[8][4];
#pragma unroll
    for (int s = 0; s < 8; s++) {
        aq[s][0] = __float_as_uint(__ldg(qb + (size_t)g       * D_ + s * 8 + c));
        aq[s][1] = __float_as_uint(__ldg(qb + (size_t)(g + 8) * D_ + s * 8 + c));
        aq[s][2] = __float_as_uint(__ldg(qb + (size_t)g       * D_ + s * 8 + c + 4));
        aq[s][3] = __float_as_uint(__ldg(qb + (size_t)(g + 8) * D_ + s * 8 + c + 4));
    }

    __syncthreads();   // pass-1 smem reads done before aliased pass-2 fills

    // ---------------- PASS 2: attn write + O = P@V (bf16 PV) ----------------
    float4 O[8];
#pragma unroll
    for (int j = 0; j < 8; j++) O[j] = make_float4(0.f, 0.f, 0.f, 0.f);

    issueK(0, 0); issueV(0, 0); cpcommit();
    buf = 0;
    for (int kt = 0; kt < L_; kt += 64) {
        cpwait0();
        __syncthreads();
        if (kt + 64 < L_) { issueK(buf ^ 1, kt + 64); issueV(buf ^ 1, kt + 64); cpcommit(); }

        const uint32_t* Kb = Ks + buf * KT32;
        const uint32_t* Vb = Vs + buf * VT32;
        float4 S[8];
#pragma unroll
        for (int j = 0; j < 8; j++) S[j] = make_float4(0.f, 0.f, 0.f, 0.f);
#pragma unroll
        for (int s = 0; s < 8; s++) {
#pragma unroll
            for (int j = 0; j < 8; j++) {
                uint2 bb = *(const uint2*)&Kb[(j * 8 + g) * KROW + s * 8 + c2];
                mma8(S[j], aq[s][0], aq[s][1], aq[s][2], aq[s][3], bb.x, bb.y);
            }
        }

        unsigned long long w0 = mp0[kt >> 6], w1 = mp1[kt >> 6];
        bool anymask = (w0 | w1) != 0ull;
        uint32_t pa[8], pb[8];
#pragma unroll
        for (int j = 0; j < 8; j++) {
            float px = ex2f(S[j].x) * inv0;
            float py = ex2f(S[j].y) * inv0;
            float pz = ex2f(S[j].z) * inv1;
            float pw = ex2f(S[j].w) * inv1;
            if (anymask) {
                int bi = j * 8 + c2;
                if ((w0 >> bi)       & 1) px = 0.f;
                if ((w0 >> (bi + 1)) & 1) py = 0.f;
                if ((w1 >> bi)       & 1) pz = 0.f;
                if ((w1 >> (bi + 1)) & 1) pw = 0.f;
            }
            int kcol = kt + j * 8 + c2;
            if (write_attn) {
                *(float2*)(attn + ((size_t)bh * L_ + qg0) * L_ + kcol) = make_float2(px, py);
                *(float2*)(attn + ((size_t)bh * L_ + qg1) * L_ + kcol) = make_float2(pz, pw);
            }
            pa[j] = packbf(px, py);
            pb[j] = packbf(pz, pw);
        }

        // O += P @ V : m16n8k16 bf16; A-frags direct from pa/pb
#pragma unroll
        for (int s = 0; s < 4; s++) {
            uint32_t a0 = pa[2 * s],     a1 = pb[2 * s];
            uint32_t a2 = pa[2 * s + 1], a3 = pb[2 * s + 1];
#pragma unroll
            for (int j = 0; j < 8; j++) {
                uint32_t b0 = Vb[(j * 8 + g) * VROW + s * 8 + c];
                uint32_t b1 = Vb[(j * 8 + g) * VROW + s * 8 + c + 4];
                mma16(O[j], a0, a1, a2, a3, b0, b1);
            }
        }
        buf ^= 1;
    }

    // ctx write: perm8 on d + tf32-round (oproj A-operand layout)
    float* cb0 = ctx + ((size_t)(b * L_ + qg0)) * D_ + h * DKV;
    float* cb1 = cb0 + (size_t)8 * D_;
#pragma unroll
    for (int j = 0; j < 8; j++) {
        int p0 = perm8(j * 8 + c2);
        int p1 = perm8(j * 8 + c2 + 1);
        cb0[p0] = rndf(O[j].x);
        cb0[p1] = rndf(O[j].y);
        cb1[p0] = rndf(O[j].z);
        cb1[p1] = rndf(O[j].w);
    }
}

// ---------------------------------------------------------------------------
// LayerNorm over D_=1024
// ---------------------------------------------------------------------------
__device__ __forceinline__ float warp_sum(float v) {
#pragma unroll
    for (int o = 16; o; o >>= 1) v += __shfl_xor_sync(0xffffffffu, v, o);
    return v;
}

__global__ __launch_bounds__(256) void ln_kernel(
    const float* __restrict__ X, const float* __restrict__ gamma,
    const float* __restrict__ beta, float* __restrict__ O)
{
    const float* x = X + (size_t)blockIdx.x * D_;
    const int tid = threadIdx.x;
    __shared__ float rs[8], rq[8];

    float4 v = *(const float4*)(x + tid * 4);
    float s  = v.x + v.y + v.z + v.w;
    float q2 = v.x * v.x + v.y * v.y + v.z * v.z + v.w * v.w;
    s  = warp_sum(s);
    q2 = warp_sum(q2);
    if ((tid & 31) == 0) { rs[tid >> 5] = s; rq[tid >> 5] = q2; }
    __syncthreads();
    float S = 0.f, Q = 0.f;
#pragma unroll
    for (int w = 0; w < 8; w++) { S += rs[w]; Q += rq[w]; }
    float mu  = S * (1.0f / D_);
    float var = Q * (1.0f / D_) - mu * mu;
    float inv = rsqrtf(var + 1e-5f);

    float4 gmm = *(const float4*)(gamma + tid * 4);
    float4 bb  = *(const float4*)(beta + tid * 4);
    float4 o;
    o.x = (v.x - mu) * inv * gmm.x + bb.x;
    o.y = (v.y - mu) * inv * gmm.y + bb.y;
    o.z = (v.z - mu) * inv * gmm.z + bb.z;
    o.w = (v.w - mu) * inv * gmm.w + bb.w;
    *(float4*)(O + (size_t)blockIdx.x * D_ + tid * 4) = o;
}

// ---------------------------------------------------------------------------
// Launch
// ---------------------------------------------------------------------------
extern "C" void kernel_launch(void* const* d_in, const int* in_sizes, int n_in,
                              void* d_out, int out_size)
{
    const float*         q     = (const float*)d_in[0];
    const float*         k     = (const float*)d_in[1];
    const float*         v     = (const float*)d_in[2];
    const unsigned char* mask  = (const unsigned char*)d_in[4];
    const float*         Wq    = (const float*)d_in[5];
    const float*         bq    = (const float*)d_in[6];
    const float*         Wk    = (const float*)d_in[7];
    const float*         bk    = (const float*)d_in[8];
    const float*         Wv    = (const float*)d_in[9];
    const float*         bv    = (const float*)d_in[10];
    const float*         Wo    = (const float*)d_in[11];
    const float*         bo    = (const float*)d_in[12];
    const float*         gamma = (const float*)d_in[13];
    const float*         beta  = (const float*)d_in[14];
    float*               out   = (float*)d_out;

    float *ap, *qh, *kh, *vh, *ctx, *xb, *wt;
    uint16_t *vtb, *khb;
    unsigned long long* mpck;
    cudaGetSymbolAddress((void**)&ap,   g_ap);
    cudaGetSymbolAddress((void**)&qh,   g_qh);
    cudaGetSymbolAddress((void**)&kh,   g_kh);
    cudaGetSymbolAddress((void**)&khb,  g_khb);
    cudaGetSymbolAddress((void**)&vh,   g_vh);
    cudaGetSymbolAddress((void**)&vtb,  g_vtb);
    cudaGetSymbolAddress((void**)&ctx,  g_ctx);
    cudaGetSymbolAddress((void**)&xb,   g_x);
    cudaGetSymbolAddress((void**)&wt,   g_wt);
    cudaGetSymbolAddress((void**)&mpck, g_mp);

    const size_t n_out  = (size_t)B_ * L_ * D_;
    const size_t n_attn = (size_t)B_ * H_ * L_ * L_;
    int write_attn = ((size_t)out_size >= n_out + n_attn) ? 1 : 0;
    float* attn = write_attn ? out + n_out : nullptr;

    const int GEMM_SMEM = (2 * 128 * 40 + 2 * 128 * 36) * 4;   // 77824
    const int ATTN_SMEM = (2 * KT32 + 2 * VT32) * 4;           // 55296
    cudaFuncSetAttribute(qkv_gemm,    cudaFuncAttributeMaxDynamicSharedMemorySize, GEMM_SMEM);
    cudaFuncSetAttribute(oproj_gemm,  cudaFuncAttributeMaxDynamicSharedMemorySize, GEMM_SMEM);
    cudaFuncSetAttribute(attn_kernel, cudaFuncAttributeMaxDynamicSharedMemorySize, ATTN_SMEM);

    wt_kernel<<<dim3(D_ / 32, D_ / 32, 4), 256>>>(Wq, Wk, Wv, Wo, wt);
    aperm_kernel<<<dim3((B_ * L_ * D_ / 8) / 256, 1, 3), 256>>>(q, k, v, ap);
    pack_mask<<<(B_ * L_ * 32 + 255) / 256, 256>>>(mask, mpck);

    const int M = B_ * L_;                 // 8192
    dim3 gqkv(D_ / 128, M / 128, 3);

    qkv_gemm<<<gqkv, 256, GEMM_SMEM>>>(
        ap, ap + (size_t)B_ * L_ * D_, ap + (size_t)2 * B_ * L_ * D_,
        wt + 0 * D_ * D_, wt + 1 * D_ * D_, wt + 2 * D_ * D_,
        bq, bk, bv, qh, kh, khb, vh);

    vtrans_kernel<<<dim3(L_ / 32, DKV / 32, B_ * H_), 256>>>(vh, vtb);

    attn_kernel<<<dim3(L_ / 128, B_ * H_), 256, ATTN_SMEM>>>(qh, kh, khb, vtb, mpck, attn, ctx, write_attn);

    oproj_gemm<<<dim3(D_ / 128, M / 128), 256, GEMM_SMEM>>>(ctx, wt + 3 * D_ * D_, bo, q, xb);
    ln_kernel<<<M, 256>>>(xb, gamma, beta, out);
}